// round 12
// baseline (speedup 1.0000x reference)
#include <cuda_runtime.h>
#include <math.h>

// Shapes: logits (4, 257, 131072) f32, advantages (4,) f32,
//         input_ids (4, 257) i32, labels (4, 257) i32
// Output: [loss(1) | per_token_logps(4*256) | avg_entropy_per_sample(4) | avg_entropy_truncated(4)]

#define THREADS 512
constexpr int BB  = 4;
constexpr int TT  = 257;
constexpr int TM1 = 256;
constexpr int VV  = 131072;
constexpr int NROWS = BB * TM1;  // 1024
// analytic correction: -sum p*log(p+eps) = H - sum p*log1p(eps/p) ~= H - V*eps
constexpr float ENT_CORR = 131072.0f * 1e-9f;

// accumulators: [ m(4) | H*m(4) | H*ecm(4) | ecm(4) ]  — reset by last CTA
__device__ float    g_acc[16];
__device__ unsigned g_done = 0;

__global__ __launch_bounds__(THREADS) void fused_kernel(
    const float* __restrict__ logits,
    const float* __restrict__ advantages,
    const int*   __restrict__ input_ids,
    const int*   __restrict__ labels,
    float*       __restrict__ out)
{
    const int row = blockIdx.x;          // 0..1023
    const int b = row >> 8;
    const int t = row & 255;
    const size_t row_off = (size_t)(b * TT + t) * VV;
    const float4* rp = reinterpret_cast<const float4*>(logits + row_off);

    const int tid  = threadIdx.x;
    const int warp = tid >> 5;
    const int lane = tid & 31;

    // Prefetch chosen logit early so its dependent LDG chain overlaps the loop.
    float xc = 0.0f;
    if (tid == 0) {
        const int chosen = input_ids[b * TT + t + 1];
        xc = logits[row_off + (size_t)chosen];
    }

    // ---- label-only phase: this row's valid flag and inclusive cumsum ----
    // Thread i (<256) checks labels[b, i+1]; cum = #valid among t' <= t.
    __shared__ int s_valid_t;
    int myvalid = 0;
    if (tid < TM1) myvalid = (labels[b * TT + tid + 1] == 1) ? 1 : 0;
    if (tid == t) s_valid_t = myvalid;
    const int cum = __syncthreads_count((tid <= t) ? myvalid : 0);
    // (the barrier inside __syncthreads_count publishes s_valid_t)

    float s = 0.0f;   // sum exp(x)
    float w = 0.0f;   // sum x * exp(x)

    // VV/4 = 32768 float4 per row; 2 float4 per thread per iter (high MLP).
    #pragma unroll 4
    for (int k = tid; k < VV / 8; k += THREADS) {
        float4 v0 = rp[k];
        float4 v1 = rp[k + VV / 8];
        float e0 = __expf(v0.x);
        float e1 = __expf(v0.y);
        float e2 = __expf(v0.z);
        float e3 = __expf(v0.w);
        float e4 = __expf(v1.x);
        float e5 = __expf(v1.y);
        float e6 = __expf(v1.z);
        float e7 = __expf(v1.w);
        s += ((e0 + e1) + (e2 + e3)) + ((e4 + e5) + (e6 + e7));
        w = fmaf(v0.x, e0, w);
        w = fmaf(v0.y, e1, w);
        w = fmaf(v0.z, e2, w);
        w = fmaf(v0.w, e3, w);
        w = fmaf(v1.x, e4, w);
        w = fmaf(v1.y, e5, w);
        w = fmaf(v1.z, e6, w);
        w = fmaf(v1.w, e7, w);
    }

    // warp reduction
    #pragma unroll
    for (int off = 16; off; off >>= 1) {
        s += __shfl_down_sync(0xffffffff, s, off);
        w += __shfl_down_sync(0xffffffff, w, off);
    }

    __shared__ float ss[16], sw[16];
    if (lane == 0) { ss[warp] = s; sw[warp] = w; }
    __syncthreads();

    if (tid != 0 && warp != 0) return;   // only warp 0 continues

    if (warp == 0) {
        s = (lane < 16) ? ss[lane] : 0.0f;
        w = (lane < 16) ? sw[lane] : 0.0f;
        #pragma unroll
        for (int off = 8; off; off >>= 1) {
            s += __shfl_down_sync(0xffffffff, s, off);
            w += __shfl_down_sync(0xffffffff, w, off);
        }
    }
    if (tid != 0) return;

    // ---- per-row epilogue (thread 0 only) ----
    const float lse = logf(s);
    const float H = lse - w / s - ENT_CORR;      // token_entropy
    out[1 + row] = xc - lse;                     // per_token_logps (TEMP=1)

    const bool valid = (s_valid_t != 0);
    const bool ecm   = valid && (cum >= 4) && (cum <= 100);
    if (valid) {
        atomicAdd(&g_acc[b],     1.0f);          // mask sum
        atomicAdd(&g_acc[4 + b], H);             // H * mask
    }
    if (ecm) {
        atomicAdd(&g_acc[8 + b],  H);            // H * ecm
        atomicAdd(&g_acc[12 + b], 1.0f);         // ecm count
    }
    __threadfence();                              // publish before counter

    if (atomicAdd(&g_done, 1u) == (unsigned)(NROWS - 1)) {
        // ---- last CTA: scalar finalize (~16 L2 loads) ----
        float acc[16];
        #pragma unroll
        for (int i = 0; i < 16; i++) acc[i] = __ldcg(&g_acc[i]);

        float num = 0.f, den = 0.f;
        #pragma unroll
        for (int i = 0; i < BB; i++) {
            out[1 + NROWS + i]      = acc[4 + i] / acc[i];        // avg_entropy_per_sample
            out[1 + NROWS + BB + i] = acc[8 + i] / acc[12 + i];   // avg_entropy_truncated
            num += advantages[i] * acc[i];
            den += acc[i];
        }
        // ratio == 1 exactly => clipped == 1 => per_token_loss = -adv[b]
        out[0] = -num / den;

        // reset for next graph replay
        #pragma unroll
        for (int i = 0; i < 16; i++) g_acc[i] = 0.0f;
        g_done = 0;
    }
}

extern "C" void kernel_launch(void* const* d_in, const int* in_sizes, int n_in,
                              void* d_out, int out_size)
{
    const float* logits     = (const float*)d_in[0];
    const float* advantages = (const float*)d_in[1];
    const int*   input_ids  = (const int*)d_in[2];
    const int*   labels     = (const int*)d_in[3];
    float* out = (float*)d_out;

    fused_kernel<<<NROWS, THREADS>>>(logits, advantages, input_ids, labels, out);
}

// round 13
// speedup vs baseline: 1.0173x; 1.0173x over previous
#include <cuda_runtime.h>
#include <math.h>

// Shapes: logits (4, 257, 131072) f32, advantages (4,) f32,
//         input_ids (4, 257) i32, labels (4, 257) i32
// Output: [loss(1) | per_token_logps(4*256) | avg_entropy_per_sample(4) | avg_entropy_truncated(4)]

#define THREADS 512
constexpr int BB  = 4;
constexpr int TT  = 257;
constexpr int TM1 = 256;
constexpr int VV  = 131072;
constexpr int NROWS = BB * TM1;  // 1024
// analytic correction: -sum p*log(p+eps) = H - sum p*log1p(eps/p) ~= H - V*eps
constexpr float ENT_CORR = 131072.0f * 1e-9f;

// accumulators: [ m(4) | H*m(4) | H*ecm(4) | ecm(4) ]  — reset by last CTA
__device__ float    g_acc[16];
__device__ unsigned g_done = 0;

__global__ __launch_bounds__(THREADS, 4) void fused_kernel(
    const float* __restrict__ logits,
    const float* __restrict__ advantages,
    const int*   __restrict__ input_ids,
    const int*   __restrict__ labels,
    float*       __restrict__ out)
{
    const int row = blockIdx.x;          // 0..1023
    const int b = row >> 8;
    const int t = row & 255;
    const size_t row_off = (size_t)(b * TT + t) * VV;
    const float4* rp = reinterpret_cast<const float4*>(logits + row_off);

    const int tid  = threadIdx.x;
    const int warp = tid >> 5;
    const int lane = tid & 31;

    // Prefetch chosen logit early so its dependent LDG chain overlaps the loop.
    float xc = 0.0f;
    if (tid == 0) {
        const int chosen = input_ids[b * TT + t + 1];
        xc = logits[row_off + (size_t)chosen];
    }

    float s = 0.0f;   // sum exp(x)
    float w = 0.0f;   // sum x * exp(x)

    // VV/4 = 32768 float4 per row; 2 float4 per thread per iter (high MLP).
    #pragma unroll 4
    for (int k = tid; k < VV / 8; k += THREADS) {
        float4 v0 = rp[k];
        float4 v1 = rp[k + VV / 8];
        float e0 = __expf(v0.x);
        float e1 = __expf(v0.y);
        float e2 = __expf(v0.z);
        float e3 = __expf(v0.w);
        float e4 = __expf(v1.x);
        float e5 = __expf(v1.y);
        float e6 = __expf(v1.z);
        float e7 = __expf(v1.w);
        s += ((e0 + e1) + (e2 + e3)) + ((e4 + e5) + (e6 + e7));
        w = fmaf(v0.x, e0, w);
        w = fmaf(v0.y, e1, w);
        w = fmaf(v0.z, e2, w);
        w = fmaf(v0.w, e3, w);
        w = fmaf(v1.x, e4, w);
        w = fmaf(v1.y, e5, w);
        w = fmaf(v1.z, e6, w);
        w = fmaf(v1.w, e7, w);
    }

    // warp reduction
    #pragma unroll
    for (int off = 16; off; off >>= 1) {
        s += __shfl_down_sync(0xffffffff, s, off);
        w += __shfl_down_sync(0xffffffff, w, off);
    }

    __shared__ float ss[16], sw[16];
    if (lane == 0) { ss[warp] = s; sw[warp] = w; }
    __syncthreads();

    if (warp != 0) return;   // only warp 0 continues

    s = (lane < 16) ? ss[lane] : 0.0f;
    w = (lane < 16) ? sw[lane] : 0.0f;
    #pragma unroll
    for (int off = 8; off; off >>= 1) {
        s += __shfl_down_sync(0xffffffff, s, off);
        w += __shfl_down_sync(0xffffffff, w, off);
    }

    // ---- label phase (warp 0, AFTER the hot loop; labels are L2-hot) ----
    // cum = #valid among t' <= t for this batch; valid = valid flag at t.
    int cnt = 0;
    int valid_t = 0;
    #pragma unroll
    for (int j = 0; j < 8; j++) {
        const int idx = j * 32 + lane;                    // 0..255
        const int lab = (labels[b * TT + idx + 1] == 1) ? 1 : 0;
        const unsigned bal = __ballot_sync(0xffffffffu, lab);
        const int rel = t - j * 32;
        if (rel >= 0) {
            const unsigned mask = (rel >= 31) ? 0xffffffffu : ((2u << rel) - 1u);
            cnt += __popc(bal & mask);
            if (rel < 32) valid_t = (bal >> rel) & 1;
        }
    }

    if (lane != 0) return;

    // ---- per-row epilogue (thread 0 only) ----
    const float lse = logf(s);
    const float H = lse - w / s - ENT_CORR;      // token_entropy
    out[1 + row] = xc - lse;                     // per_token_logps (TEMP=1)

    const bool valid = (valid_t != 0);
    const bool ecm   = valid && (cnt >= 4) && (cnt <= 100);
    if (valid) {
        atomicAdd(&g_acc[b],     1.0f);          // mask sum
        atomicAdd(&g_acc[4 + b], H);             // H * mask
    }
    if (ecm) {
        atomicAdd(&g_acc[8 + b],  H);            // H * ecm
        atomicAdd(&g_acc[12 + b], 1.0f);         // ecm count
    }
    __threadfence();                              // publish before counter

    if (atomicAdd(&g_done, 1u) == (unsigned)(NROWS - 1)) {
        // ---- last CTA: scalar finalize (~16 L2 loads) ----
        float acc[16];
        #pragma unroll
        for (int i = 0; i < 16; i++) acc[i] = __ldcg(&g_acc[i]);

        float num = 0.f, den = 0.f;
        #pragma unroll
        for (int i = 0; i < BB; i++) {
            out[1 + NROWS + i]      = acc[4 + i] / acc[i];        // avg_entropy_per_sample
            out[1 + NROWS + BB + i] = acc[8 + i] / acc[12 + i];   // avg_entropy_truncated
            num += advantages[i] * acc[i];
            den += acc[i];
        }
        // ratio == 1 exactly => clipped == 1 => per_token_loss = -adv[b]
        out[0] = -num / den;

        // reset for next graph replay
        #pragma unroll
        for (int i = 0; i < 16; i++) g_acc[i] = 0.0f;
        g_done = 0;
    }
}

extern "C" void kernel_launch(void* const* d_in, const int* in_sizes, int n_in,
                              void* d_out, int out_size)
{
    const float* logits     = (const float*)d_in[0];
    const float* advantages = (const float*)d_in[1];
    const int*   input_ids  = (const int*)d_in[2];
    const int*   labels     = (const int*)d_in[3];
    float* out = (float*)d_out;

    fused_kernel<<<NROWS, THREADS>>>(logits, advantages, input_ids, labels, out);
}